// round 10
// baseline (speedup 1.0000x reference)
#include <cuda_runtime.h>
#include <stdint.h>

// Fp8Unpadding: gather un-padded rows out of a 256-row-padded concatenation.
// M_SPLITS = {1000,2300,512,3777,129,2048,900,1500}, HIDDEN=4096 (f32).
// dst row r maps to src row r + DELTA[group(r)]; DELTA constant per group.
//
// Row boundaries (cumulative m):  1000, 3300, 3812, 7589, 7718, 9766, 10666, 12166
// Row deltas:                        0,   24,   28,   28,   91,  218,   218,   342
//
// FINAL config (R6 family): one 16KB row per block. TPB=128, 8x float4 per
// thread = 1024 v4 = exactly 1 row. Block-uniform delta, front-batched loads
// (MLP=8), zero tail. R10 micro-probe: loads use .lu (last-use) instead of
// .cs — line is dead after read, lets L2 drop it immediately and keep LTS
// capacity for the write stream.
//
// Roofline status: 6304 GB/s == measured B300 LTS chip cap (~6300 B/cyc,
// path-independent). Saturated; limit is the LTS fabric, not the kernel.

static constexpr int HIDDEN_V4  = 4096 / 4;   // 1024 float4 per row
static constexpr int TOTAL_ROWS = 12166;
static constexpr int UNROLL     = 8;
static constexpr int TPB        = 128;        // TPB * UNROLL = 1024 = 1 row

__device__ __forceinline__ int row_delta(int row)
{
    return (row < 1000)  ? 0
         : (row < 3300)  ? 24
         : (row < 7589)  ? 28
         : (row < 7718)  ? 91
         : (row < 10666) ? 218
         :                 342;
}

__device__ __forceinline__ float4 ld128_lu(const float4* p)
{
    float4 r;
    asm volatile("ld.global.lu.v4.f32 {%0,%1,%2,%3}, [%4];"
                 : "=f"(r.x), "=f"(r.y), "=f"(r.z), "=f"(r.w)
                 : "l"(p));
    return r;
}

__global__ void __launch_bounds__(TPB)
unpad_gather_kernel(const float4* __restrict__ in, float4* __restrict__ out)
{
    int row = blockIdx.x;                        // one row per block
    const float4* __restrict__ src = in  + (row + row_delta(row)) * HIDDEN_V4;
    float4*       __restrict__ dst = out + row * HIDDEN_V4;

    float4 v[UNROLL];

    // front-batched independent loads (deep MLP), last-use policy
    #pragma unroll
    for (int j = 0; j < UNROLL; j++)
        v[j] = ld128_lu(src + j * TPB + threadIdx.x);

    #pragma unroll
    for (int j = 0; j < UNROLL; j++)
        __stcs(dst + j * TPB + threadIdx.x, v[j]);
}

extern "C" void kernel_launch(void* const* d_in, const int* in_sizes, int n_in,
                              void* d_out, int out_size)
{
    const float4* in  = (const float4*)d_in[0];   // f32 [12544, 4096]
    float4*       out = (float4*)d_out;           // f32 [12166, 4096]

    unpad_gather_kernel<<<TOTAL_ROWS, TPB>>>(in, out);
}